// round 7
// baseline (speedup 1.0000x reference)
#include <cuda_runtime.h>

// GaussianPooling: out[n,c] = sum_{dy,dx} fm[c, y+dy, x+dx] * kern[dy,dx]
// fm: [512,256,256] f32, keypoints: [4096,2] int (x,y), out: [4096,512] f32.
// Separable 5x5 Gaussian (sigma=2).
//
// prep: 128 blocks (8 stripes x 16 keypoint-slices) bin keypoints into
//       per-(stripe,part) queues; early PDL trigger.
// main: block = (stripe of 32 rows, channel pair). Vertical conv
//       global->SMEM (channels interleaved for 2x MLP), then per keypoint
//       one horizontal dot per channel; STG.64 output. PDL-overlapped.

#define C_DIM 512
#define H_DIM 256
#define W_DIM 256
#define N_KP  4096
#define PLANE (H_DIM * W_DIM)
#define STRIPE_ROWS 32
#define N_STRIPES (H_DIM / STRIPE_ROWS)          // 8
#define N_PARTS 16
#define PART_KP (N_KP / N_PARTS)                 // 256
#define SM_STRIDE 260                            // 256 + 4 pad
#define V_FLOATS (STRIPE_ROWS * SM_STRIDE)       // 8320 per channel
#define CG 2
#define SMEM_BYTES (CG * V_FLOATS * 4)           // 66560

__device__ int g_q[N_STRIPES * N_PARTS * PART_KP];  // packed (n<<16)|(x<<8)|y
__device__ int g_qcnt[N_STRIPES * N_PARTS];

static __device__ __forceinline__ float gval(float i) {
    float d = i - 2.0f;
    return __expf(-d * d * 0.125f);              // exp(-d^2/(2*sigma^2))
}

// grid = 8 stripes x 16 parts. Each block scans its 256-keypoint slice for
// its stripe. dtype detect per slice: words kp32[2n+1] are y (int32 case,
// random nonzero) or int64 high halves (all zero).
__global__ void prep_kp_kernel(const int* __restrict__ kp32)
{
    __shared__ int s_or[256];
    __shared__ int s_flag;
    __shared__ int s_cnt;
    const int t      = threadIdx.x;
    const int stripe = blockIdx.x >> 4;
    const int part   = blockIdx.x & (N_PARTS - 1);
    const int n      = part * PART_KP + t;       // 256 threads = 256 kps

    s_or[t] = kp32[2 * n + 1];
    if (t == 0) s_cnt = 0;
    __syncthreads();
    for (int s = 128; s > 0; s >>= 1) {
        if (t < s) s_or[t] |= s_or[t + s];
        __syncthreads();
    }
    if (t == 0) s_flag = s_or[0];
    __syncthreads();
    const bool is_i32 = (s_flag != 0);

    int x, y;
    if (is_i32) { x = kp32[2 * n];     y = kp32[2 * n + 1]; }
    else        { x = kp32[4 * n];     y = kp32[4 * n + 2]; }
    x = min(max(x, 2), W_DIM - 3);
    y = min(max(y, 2), H_DIM - 3);

    if ((y >> 5) == stripe) {
        int idx = atomicAdd(&s_cnt, 1);
        g_q[(stripe * N_PARTS + part) * PART_KP + idx] =
            (n << 16) | (x << 8) | y;
    }
    __syncthreads();
    if (t == 0) g_qcnt[stripe * N_PARTS + part] = s_cnt;

    // Let the PDL-dependent main kernel's gridDependencySynchronize release
    // as soon as all prep blocks reach here (writes above are visible).
    cudaTriggerProgrammaticLaunchCompletion();
}

__global__ void __launch_bounds__(256)
gauss_pool_kernel(const float* __restrict__ fm, float* __restrict__ out)
{
    extern __shared__ float s_v[];               // CG tiles of [32][SM_STRIDE]
    __shared__ float s_gx[4][8];

    const int cg0    = (blockIdx.x & 255) * CG;
    const int stripe = blockIdx.x >> 8;
    const int t      = threadIdx.x;
    const int row0   = stripe * STRIPE_ROWS - 2;

    const float inv_norm =
        1.0f / (gval(0.f) + gval(1.f) + gval(2.f) + gval(3.f) + gval(4.f));

    if (t < 32) {
        int off = t >> 3, j = t & 7;
        int i = j - off;
        s_gx[off][j] = (i >= 0 && i < 5) ? gval((float)i) * inv_norm : 0.0f;
    }

    const float g0 = gval(0.f) * inv_norm;
    const float g1 = gval(1.f) * inv_norm;
    const float g2 = gval(2.f) * inv_norm;

    // ---- Phase 1: vertical conv, both channels interleaved (2x MLP) ----
    // thread = (chunk = t>>6 covering 8 V-rows, strip = t&63 float4 column)
    {
        const int strip = t & 63;
        const int chunk = t >> 6;
        const int L0    = chunk * 8;
        const float4* pl0 = (const float4*)(fm + (size_t)cg0 * PLANE) + strip;
        const float4* pl1 = pl0 + PLANE / 4;
        float* tile0 = s_v;
        float* tile1 = s_v + V_FLOATS;

        float4 a0, a1, a2, a3, a4;               // ch0 rolling window
        float4 b0, b1, b2, b3, b4;               // ch1 rolling window
        #pragma unroll
        for (int k = 0; k < 12; ++k) {
            const int li = L0 + k;
            const int gr = min(max(row0 + li, 0), H_DIM - 1);
            float4 u = pl0[gr * (W_DIM / 4)];
            float4 w = pl1[gr * (W_DIM / 4)];
            a0 = a1; a1 = a2; a2 = a3; a3 = a4; a4 = u;
            b0 = b1; b1 = b2; b2 = b3; b3 = b4; b4 = w;
            if (k >= 4) {
                const int vi = li - 4;
                float4 r;
                r.x = g0 * (a0.x + a4.x) + g1 * (a1.x + a3.x) + g2 * a2.x;
                r.y = g0 * (a0.y + a4.y) + g1 * (a1.y + a3.y) + g2 * a2.y;
                r.z = g0 * (a0.z + a4.z) + g1 * (a1.z + a3.z) + g2 * a2.z;
                r.w = g0 * (a0.w + a4.w) + g1 * (a1.w + a3.w) + g2 * a2.w;
                *(float4*)&tile0[vi * SM_STRIDE + strip * 4] = r;
                float4 s;
                s.x = g0 * (b0.x + b4.x) + g1 * (b1.x + b3.x) + g2 * b2.x;
                s.y = g0 * (b0.y + b4.y) + g1 * (b1.y + b3.y) + g2 * b2.y;
                s.z = g0 * (b0.z + b4.z) + g1 * (b1.z + b3.z) + g2 * b2.z;
                s.w = g0 * (b0.w + b4.w) + g1 * (b1.w + b3.w) + g2 * b2.w;
                *(float4*)&tile1[vi * SM_STRIDE + strip * 4] = s;
            }
        }
    }

    cudaGridDependencySynchronize();             // queues ready (PDL)
    __syncthreads();

    // ---- Phase 2: per-keypoint horizontal dot, one row per channel ----
    #pragma unroll 1
    for (int p = 0; p < N_PARTS; ++p) {
        const int qi  = stripe * N_PARTS + p;
        const int cnt = g_qcnt[qi];
        const int* q  = &g_q[qi * PART_KP];

        for (int i = t; i < cnt; i += 256) {
            const int v = q[i];
            const int y = v & 255;
            const int x = (v >> 8) & 255;
            const int n = v >> 16;

            const int w0c = x - 2;
            const int a   = w0c & ~3;
            const int off = w0c - a;
            const int yl  = y - stripe * STRIPE_ROWS;
            const float* gx = s_gx[off];

            const float* base0 = s_v + yl * SM_STRIDE + a;
            float4 A = *(const float4*)(base0);
            float4 B = *(const float4*)(base0 + 4);
            const float* base1 = base0 + V_FLOATS;
            float4 C = *(const float4*)(base1);
            float4 D = *(const float4*)(base1 + 4);

            float2 res;
            res.x = gx[0] * A.x + gx[1] * A.y + gx[2] * A.z + gx[3] * A.w
                  + gx[4] * B.x + gx[5] * B.y + gx[6] * B.z + gx[7] * B.w;
            res.y = gx[0] * C.x + gx[1] * C.y + gx[2] * C.z + gx[3] * C.w
                  + gx[4] * D.x + gx[5] * D.y + gx[6] * D.z + gx[7] * D.w;

            *(float2*)&out[n * C_DIM + cg0] = res;
        }
    }
}

extern "C" void kernel_launch(void* const* d_in, const int* in_sizes, int n_in,
                              void* d_out, int out_size)
{
    const float* fm   = (const float*)d_in[0];
    const int*   kp32 = (const int*)d_in[1];
    float*       out  = (float*)d_out;

    cudaFuncSetAttribute(gauss_pool_kernel,
                         cudaFuncAttributeMaxDynamicSharedMemorySize,
                         SMEM_BYTES);

    prep_kp_kernel<<<N_STRIPES * N_PARTS, 256>>>(kp32);

    cudaLaunchConfig_t cfg = {};
    cfg.gridDim  = dim3(N_STRIPES * (C_DIM / CG));
    cfg.blockDim = dim3(256);
    cfg.dynamicSmemBytes = SMEM_BYTES;
    cfg.stream = 0;
    cudaLaunchAttribute attr[1];
    attr[0].id = cudaLaunchAttributeProgrammaticStreamSerialization;
    attr[0].val.programmaticStreamSerializationAllowed = 1;
    cfg.attrs = attr;
    cfg.numAttrs = 1;
    cudaLaunchKernelEx(&cfg, gauss_pool_kernel, fm, out);
}

// round 8
// speedup vs baseline: 1.4451x; 1.4451x over previous
#include <cuda_runtime.h>

// GaussianPooling: out[n,c] = sum_{dy,dx} fm[c, y+dy, x+dx] * kern[dy,dx]
// fm: [512,256,256] f32, keypoints: [4096,2] int (x,y), out: [4096,512] f32.
// Separable 5x5 Gaussian (sigma=2).
//
// prep: 128 blocks (8 stripes x 16 keypoint-slices) bin keypoints into
//       per-(stripe,part) queues; early PDL trigger.
// main: block = (stripe of 32 rows, channel pair). Vertical conv
//       global->SMEM per channel, then per keypoint one horizontal dot per
//       channel; STG.64 output. Phase 2: one warp per queue part.

#define C_DIM 512
#define H_DIM 256
#define W_DIM 256
#define N_KP  4096
#define PLANE (H_DIM * W_DIM)
#define STRIPE_ROWS 32
#define N_STRIPES (H_DIM / STRIPE_ROWS)          // 8
#define N_PARTS 16
#define PART_KP (N_KP / N_PARTS)                 // 256
#define SM_STRIDE 260                            // 256 + 4 pad
#define V_FLOATS (STRIPE_ROWS * SM_STRIDE)       // 8320 per channel
#define CG 2
#define SMEM_BYTES (CG * V_FLOATS * 4)           // 66560

__device__ int g_q[N_STRIPES * N_PARTS * PART_KP];  // packed (n<<16)|(x<<8)|y
__device__ int g_qcnt[N_STRIPES * N_PARTS];

static __device__ __forceinline__ float gval(float i) {
    float d = i - 2.0f;
    return __expf(-d * d * 0.125f);              // exp(-d^2/(2*sigma^2))
}

// grid = 8 stripes x 16 parts. Each block scans its 256-keypoint slice for
// its stripe. dtype detect per slice: words kp32[2n+1] are y (int32 case,
// random nonzero somewhere in slice) or int64 high halves (all zero).
__global__ void prep_kp_kernel(const int* __restrict__ kp32)
{
    __shared__ int s_or[256];
    __shared__ int s_flag;
    __shared__ int s_cnt;
    const int t      = threadIdx.x;
    const int stripe = blockIdx.x >> 4;
    const int part   = blockIdx.x & (N_PARTS - 1);
    const int n      = part * PART_KP + t;

    s_or[t] = kp32[2 * n + 1];
    if (t == 0) s_cnt = 0;
    __syncthreads();
    for (int s = 128; s > 0; s >>= 1) {
        if (t < s) s_or[t] |= s_or[t + s];
        __syncthreads();
    }
    if (t == 0) s_flag = s_or[0];
    __syncthreads();
    const bool is_i32 = (s_flag != 0);

    int x, y;
    if (is_i32) { x = kp32[2 * n];     y = kp32[2 * n + 1]; }
    else        { x = kp32[4 * n];     y = kp32[4 * n + 2]; }
    x = min(max(x, 2), W_DIM - 3);
    y = min(max(y, 2), H_DIM - 3);

    if ((y >> 5) == stripe) {
        int idx = atomicAdd(&s_cnt, 1);
        g_q[(stripe * N_PARTS + part) * PART_KP + idx] =
            (n << 16) | (x << 8) | y;
    }
    __syncthreads();
    if (t == 0) g_qcnt[stripe * N_PARTS + part] = s_cnt;

    cudaTriggerProgrammaticLaunchCompletion();
}

__global__ void __launch_bounds__(256)
gauss_pool_kernel(const float* __restrict__ fm, float* __restrict__ out)
{
    extern __shared__ float s_v[];               // CG tiles of [32][SM_STRIDE]
    __shared__ float s_gx[4][8];

    const int cg0    = (blockIdx.x & 255) * CG;
    const int stripe = blockIdx.x >> 8;
    const int t      = threadIdx.x;
    const int row0   = stripe * STRIPE_ROWS - 2;

    const float inv_norm =
        1.0f / (gval(0.f) + gval(1.f) + gval(2.f) + gval(3.f) + gval(4.f));

    if (t < 32) {
        int off = t >> 3, j = t & 7;
        int i = j - off;
        s_gx[off][j] = (i >= 0 && i < 5) ? gval((float)i) * inv_norm : 0.0f;
    }

    const float g0 = gval(0.f) * inv_norm;
    const float g1 = gval(1.f) * inv_norm;
    const float g2 = gval(2.f) * inv_norm;

    // ---- Phase 1: vertical conv, global -> SMEM, per channel ----
    {
        const int strip = t & 63;
        const int chunk = t >> 6;
        const int L0    = chunk * 8;

        #pragma unroll
        for (int cg = 0; cg < CG; ++cg) {
            const float4* pl4 =
                (const float4*)(fm + (size_t)(cg0 + cg) * PLANE) + strip;
            float* tile = s_v + cg * V_FLOATS;

            float4 w0, w1, w2, w3, w4;
            #pragma unroll
            for (int k = 0; k < 12; ++k) {
                const int li = L0 + k;
                const int gr = min(max(row0 + li, 0), H_DIM - 1);
                float4 v = pl4[gr * (W_DIM / 4)];
                w0 = w1; w1 = w2; w2 = w3; w3 = w4; w4 = v;
                if (k >= 4) {
                    float4 r;
                    r.x = g0 * (w0.x + w4.x) + g1 * (w1.x + w3.x) + g2 * w2.x;
                    r.y = g0 * (w0.y + w4.y) + g1 * (w1.y + w3.y) + g2 * w2.y;
                    r.z = g0 * (w0.z + w4.z) + g1 * (w1.z + w3.z) + g2 * w2.z;
                    r.w = g0 * (w0.w + w4.w) + g1 * (w1.w + w3.w) + g2 * w2.w;
                    *(float4*)&tile[(li - 4) * SM_STRIDE + strip * 4] = r;
                }
            }
        }
    }

    cudaGridDependencySynchronize();             // queues ready (PDL)
    __syncthreads();

    // ---- Phase 2: one warp per part (16 parts, 8 warps x 2) ----
    const int warp = t >> 5;
    const int lane = t & 31;

    #pragma unroll 1
    for (int pp = 0; pp < N_PARTS / 8; ++pp) {
        const int p   = warp + pp * 8;
        const int qi  = stripe * N_PARTS + p;
        const int cnt = g_qcnt[qi];
        const int* q  = &g_q[qi * PART_KP];

        for (int i = lane; i < cnt; i += 32) {
            const int v = q[i];
            const int y = v & 255;
            const int x = (v >> 8) & 255;
            const int n = v >> 16;

            const int w0c = x - 2;
            const int a   = w0c & ~3;
            const int off = w0c - a;
            const int yl  = y - stripe * STRIPE_ROWS;
            const float* gx = s_gx[off];

            const float* base0 = s_v + yl * SM_STRIDE + a;
            float4 A = *(const float4*)(base0);
            float4 B = *(const float4*)(base0 + 4);
            const float* base1 = base0 + V_FLOATS;
            float4 C = *(const float4*)(base1);
            float4 D = *(const float4*)(base1 + 4);

            float2 res;
            res.x = gx[0] * A.x + gx[1] * A.y + gx[2] * A.z + gx[3] * A.w
                  + gx[4] * B.x + gx[5] * B.y + gx[6] * B.z + gx[7] * B.w;
            res.y = gx[0] * C.x + gx[1] * C.y + gx[2] * C.z + gx[3] * C.w
                  + gx[4] * D.x + gx[5] * D.y + gx[6] * D.z + gx[7] * D.w;

            *(float2*)&out[n * C_DIM + cg0] = res;
        }
    }
}

extern "C" void kernel_launch(void* const* d_in, const int* in_sizes, int n_in,
                              void* d_out, int out_size)
{
    const float* fm   = (const float*)d_in[0];
    const int*   kp32 = (const int*)d_in[1];
    float*       out  = (float*)d_out;

    cudaFuncSetAttribute(gauss_pool_kernel,
                         cudaFuncAttributeMaxDynamicSharedMemorySize,
                         SMEM_BYTES);

    prep_kp_kernel<<<N_STRIPES * N_PARTS, 256>>>(kp32);

    cudaLaunchConfig_t cfg = {};
    cfg.gridDim  = dim3(N_STRIPES * (C_DIM / CG));
    cfg.blockDim = dim3(256);
    cfg.dynamicSmemBytes = SMEM_BYTES;
    cfg.stream = 0;
    cudaLaunchAttribute attr[1];
    attr[0].id = cudaLaunchAttributeProgrammaticStreamSerialization;
    attr[0].val.programmaticStreamSerializationAllowed = 1;
    cfg.attrs = attr;
    cfg.numAttrs = 1;
    cudaLaunchKernelEx(&cfg, gauss_pool_kernel, fm, out);
}

// round 9
// speedup vs baseline: 1.5418x; 1.0669x over previous
#include <cuda_runtime.h>

// GaussianPooling: out[n,c] = sum_{dy,dx} fm[c, y+dy, x+dx] * kern[dy,dx]
// fm: [512,256,256] f32, keypoints: [4096,2] int (x,y), out: [4096,512] f32.
// Separable 5x5 Gaussian (sigma=2).
//
// prep: 256 blocks (16 stripes x 16 keypoint-slices) bin keypoints into
//       per-(stripe,part) queues; early PDL trigger.
// main: block = (stripe of 16 rows, channel pair), 6 blocks/SM. Vertical
//       conv global->SMEM per channel, then per keypoint one horizontal dot
//       per channel; STG.64 output. Phase 2: one warp per queue part.

#define C_DIM 512
#define H_DIM 256
#define W_DIM 256
#define N_KP  4096
#define PLANE (H_DIM * W_DIM)
#define STRIPE_ROWS 16
#define N_STRIPES (H_DIM / STRIPE_ROWS)          // 16
#define N_PARTS 16
#define PART_KP (N_KP / N_PARTS)                 // 256
#define SM_STRIDE 260                            // 256 + 4 pad
#define V_FLOATS (STRIPE_ROWS * SM_STRIDE)       // 4160 per channel
#define CG 2
#define SMEM_BYTES (CG * V_FLOATS * 4)           // 33280

__device__ int g_q[N_STRIPES * N_PARTS * PART_KP];  // packed (n<<16)|(x<<8)|y
__device__ int g_qcnt[N_STRIPES * N_PARTS];

static __device__ __forceinline__ float gval(float i) {
    float d = i - 2.0f;
    return __expf(-d * d * 0.125f);              // exp(-d^2/(2*sigma^2))
}

// grid = 16 stripes x 16 parts. Each block scans its 256-keypoint slice for
// its stripe. dtype detect per slice: words kp32[2n+1] are y (int32 case,
// random nonzero somewhere in slice) or int64 high halves (all zero).
__global__ void prep_kp_kernel(const int* __restrict__ kp32)
{
    __shared__ int s_or[256];
    __shared__ int s_flag;
    __shared__ int s_cnt;
    const int t      = threadIdx.x;
    const int stripe = blockIdx.x >> 4;
    const int part   = blockIdx.x & (N_PARTS - 1);
    const int n      = part * PART_KP + t;

    s_or[t] = kp32[2 * n + 1];
    if (t == 0) s_cnt = 0;
    __syncthreads();
    for (int s = 128; s > 0; s >>= 1) {
        if (t < s) s_or[t] |= s_or[t + s];
        __syncthreads();
    }
    if (t == 0) s_flag = s_or[0];
    __syncthreads();
    const bool is_i32 = (s_flag != 0);

    int x, y;
    if (is_i32) { x = kp32[2 * n];     y = kp32[2 * n + 1]; }
    else        { x = kp32[4 * n];     y = kp32[4 * n + 2]; }
    x = min(max(x, 2), W_DIM - 3);
    y = min(max(y, 2), H_DIM - 3);

    if ((y >> 4) == stripe) {
        int idx = atomicAdd(&s_cnt, 1);
        g_q[(stripe * N_PARTS + part) * PART_KP + idx] =
            (n << 16) | (x << 8) | y;
    }
    __syncthreads();
    if (t == 0) g_qcnt[stripe * N_PARTS + part] = s_cnt;

    cudaTriggerProgrammaticLaunchCompletion();
}

__global__ void __launch_bounds__(256, 6)
gauss_pool_kernel(const float* __restrict__ fm, float* __restrict__ out)
{
    extern __shared__ float s_v[];               // CG tiles of [16][SM_STRIDE]
    __shared__ float s_gx[4][8];

    const int cg0    = (blockIdx.x & 255) * CG;
    const int stripe = blockIdx.x >> 8;
    const int t      = threadIdx.x;
    const int row0   = stripe * STRIPE_ROWS - 2;

    const float inv_norm =
        1.0f / (gval(0.f) + gval(1.f) + gval(2.f) + gval(3.f) + gval(4.f));

    if (t < 32) {
        int off = t >> 3, j = t & 7;
        int i = j - off;
        s_gx[off][j] = (i >= 0 && i < 5) ? gval((float)i) * inv_norm : 0.0f;
    }

    const float g0 = gval(0.f) * inv_norm;
    const float g1 = gval(1.f) * inv_norm;
    const float g2 = gval(2.f) * inv_norm;

    // ---- Phase 1: vertical conv, global -> SMEM, per channel ----
    // thread = (chunk = t>>6 covering 4 V-rows, strip = t&63 float4 column)
    {
        const int strip = t & 63;
        const int chunk = t >> 6;
        const int L0    = chunk * 4;

        #pragma unroll
        for (int cg = 0; cg < CG; ++cg) {
            const float4* pl4 =
                (const float4*)(fm + (size_t)(cg0 + cg) * PLANE) + strip;
            float* tile = s_v + cg * V_FLOATS;

            float4 w0, w1, w2, w3, w4;
            #pragma unroll
            for (int k = 0; k < 8; ++k) {
                const int li = L0 + k;
                const int gr = min(max(row0 + li, 0), H_DIM - 1);
                float4 v = pl4[gr * (W_DIM / 4)];
                w0 = w1; w1 = w2; w2 = w3; w3 = w4; w4 = v;
                if (k >= 4) {
                    float4 r;
                    r.x = g0 * (w0.x + w4.x) + g1 * (w1.x + w3.x) + g2 * w2.x;
                    r.y = g0 * (w0.y + w4.y) + g1 * (w1.y + w3.y) + g2 * w2.y;
                    r.z = g0 * (w0.z + w4.z) + g1 * (w1.z + w3.z) + g2 * w2.z;
                    r.w = g0 * (w0.w + w4.w) + g1 * (w1.w + w3.w) + g2 * w2.w;
                    *(float4*)&tile[(li - 4) * SM_STRIDE + strip * 4] = r;
                }
            }
        }
    }

    cudaGridDependencySynchronize();             // queues ready (PDL)
    __syncthreads();

    // ---- Phase 2: one warp per part (16 parts, 8 warps x 2) ----
    const int warp = t >> 5;
    const int lane = t & 31;

    #pragma unroll 1
    for (int pp = 0; pp < N_PARTS / 8; ++pp) {
        const int p   = warp + pp * 8;
        const int qi  = stripe * N_PARTS + p;
        const int cnt = g_qcnt[qi];
        const int* q  = &g_q[qi * PART_KP];

        for (int i = lane; i < cnt; i += 32) {
            const int v = q[i];
            const int y = v & 255;
            const int x = (v >> 8) & 255;
            const int n = v >> 16;

            const int w0c = x - 2;
            const int a   = w0c & ~3;
            const int off = w0c - a;
            const int yl  = y - stripe * STRIPE_ROWS;
            const float* gx = s_gx[off];

            const float* base0 = s_v + yl * SM_STRIDE + a;
            float4 A = *(const float4*)(base0);
            float4 B = *(const float4*)(base0 + 4);
            const float* base1 = base0 + V_FLOATS;
            float4 C = *(const float4*)(base1);
            float4 D = *(const float4*)(base1 + 4);

            float2 res;
            res.x = gx[0] * A.x + gx[1] * A.y + gx[2] * A.z + gx[3] * A.w
                  + gx[4] * B.x + gx[5] * B.y + gx[6] * B.z + gx[7] * B.w;
            res.y = gx[0] * C.x + gx[1] * C.y + gx[2] * C.z + gx[3] * C.w
                  + gx[4] * D.x + gx[5] * D.y + gx[6] * D.z + gx[7] * D.w;

            *(float2*)&out[n * C_DIM + cg0] = res;
        }
    }
}

extern "C" void kernel_launch(void* const* d_in, const int* in_sizes, int n_in,
                              void* d_out, int out_size)
{
    const float* fm   = (const float*)d_in[0];
    const int*   kp32 = (const int*)d_in[1];
    float*       out  = (float*)d_out;

    cudaFuncSetAttribute(gauss_pool_kernel,
                         cudaFuncAttributeMaxDynamicSharedMemorySize,
                         SMEM_BYTES);

    prep_kp_kernel<<<N_STRIPES * N_PARTS, 256>>>(kp32);

    cudaLaunchConfig_t cfg = {};
    cfg.gridDim  = dim3(N_STRIPES * (C_DIM / CG));
    cfg.blockDim = dim3(256);
    cfg.dynamicSmemBytes = SMEM_BYTES;
    cfg.stream = 0;
    cudaLaunchAttribute attr[1];
    attr[0].id = cudaLaunchAttributeProgrammaticStreamSerialization;
    attr[0].val.programmaticStreamSerializationAllowed = 1;
    cfg.attrs = attr;
    cfg.numAttrs = 1;
    cudaLaunchKernelEx(&cfg, gauss_pool_kernel, fm, out);
}